// round 15
// baseline (speedup 1.0000x reference)
#include <cuda_runtime.h>
#include <cuda_bf16.h>
#include <math.h>
#include <float.h>
#include <stdint.h>

#define NMAX 100000
#define DD 512
#define QD 128
#define BBLK 64
#define TROW 80
#define TILEB 10240

// ======================= mma wrapper =======================
__device__ __forceinline__ void mma16816(float (&c)[4], const uint32_t (&a)[4],
                                         uint32_t b0, uint32_t b1) {
    asm volatile(
        "mma.sync.aligned.m16n8k16.row.col.f32.bf16.bf16.f32 "
        "{%0,%1,%2,%3}, {%4,%5,%6,%7}, {%8,%9}, {%0,%1,%2,%3};"
        : "+f"(c[0]), "+f"(c[1]), "+f"(c[2]), "+f"(c[3])
        : "r"(a[0]), "r"(a[1]), "r"(a[2]), "r"(a[3]), "r"(b0), "r"(b1));
}

// ======================= scratch (device symbols; never passed from host) ====
static __device__ float g_predsmod[NMAX];
static __device__ float g_scale[NMAX];
static __device__ __align__(16) __nv_bfloat16 g_fAh[(size_t)NMAX * DD];
static __device__ __align__(16) __nv_bfloat16 g_fAl[(size_t)NMAX * DD];
static __device__ __align__(16) __nv_bfloat16 g_fh[(size_t)NMAX * DD];
static __device__ __align__(16) __nv_bfloat16 g_fl[(size_t)NMAX * DD];
static __device__ float g_Alog[(size_t)NMAX * 2];
static __device__ __align__(16) __nv_bfloat16 g_Wlh[DD * DD], g_Wll[DD * DD];
static __device__ __align__(16) __nv_bfloat16 g_Wqh[QD * DD], g_Wql[QD * DD];

static __device__ int g_bad[3];

static __device__ unsigned g_hist[256];
static __device__ unsigned g_prefix;
static __device__ int g_krem;
static __device__ unsigned g_thresh;
static __device__ float g_pmax[256];
static __device__ float g_psum[256];
static __device__ float g_maxv;
static __device__ float g_sumv;
static __device__ float g_cpv[128 * 2];
static __device__ int g_cpi[128 * 2];
static __device__ int g_midx[2];
static __device__ float g_qmax[2 * QD];
static __device__ float g_apm[256 * 2];
static __device__ float g_aps[256 * 2];
static __device__ float g_amax[2];
static __device__ float g_asum[2];
static __device__ float g_Bpart[BBLK * 2 * DD];
static __device__ float g_T[2 * DD];
static __device__ float g_B[2 * DD];

static __device__ __forceinline__ unsigned f2key(float x) {
    unsigned u = __float_as_uint(x);
    return (u & 0x80000000u) ? ~u : (u | 0x80000000u);
}
static __device__ __forceinline__ void split2(float v, __nv_bfloat16& h, __nv_bfloat16& l) {
    h = __float2bfloat16(v);
    l = __float2bfloat16(v - __bfloat162float(h));
}
static __device__ __forceinline__ float fget(size_t idx) {
    return __bfloat162float(g_fh[idx]) + __bfloat162float(g_fl[idx]);
}
// combine two (max, sum-of-exp) pairs
static __device__ __forceinline__ void msmerge(float& m, float& s, float m2, float s2) {
    if (m2 > m) { s = s * expf(m - m2) + s2; m = m2; }
    else if (m2 > -FLT_MAX) { s = s + s2 * expf(m2 - m); }
}

// ======================= radix select =======================
__global__ void init_sel(int k) {
    g_hist[threadIdx.x] = 0u;
    if (threadIdx.x < 3) g_bad[threadIdx.x] = 0;
    if (threadIdx.x == 0) { g_prefix = 0u; g_krem = k; }
}
__global__ void hist_kernel(const float* __restrict__ preds, int n, int p) {
    __shared__ unsigned sh[256];
    sh[threadIdx.x] = 0u;
    __syncthreads();
    int shift = 24 - 8 * p;
    unsigned pref = g_prefix;
    for (int i = blockIdx.x * blockDim.x + threadIdx.x; i < n; i += gridDim.x * blockDim.x) {
        unsigned key = f2key(preds[i]);
        bool m = (p == 0) || ((key >> (shift + 8)) == pref);
        if (m) atomicAdd(&sh[(key >> shift) & 255u], 1u);
    }
    __syncthreads();
    if (sh[threadIdx.x]) atomicAdd(&g_hist[threadIdx.x], sh[threadIdx.x]);
}
__global__ void scan_kernel(int p) {
    if (threadIdx.x == 0) {
        int krem = g_krem;
        unsigned cum = 0;
        int b = 0;
        for (b = 0; b < 256; b++) {
            unsigned h = g_hist[b];
            if (cum + h >= (unsigned)krem) break;
            cum += h;
        }
        g_prefix = (g_prefix << 8) | (unsigned)b;
        g_krem = krem - (int)cum;
        if (p == 3) g_thresh = g_prefix;
    }
    __syncthreads();
    g_hist[threadIdx.x] = 0u;
}

// ======================= fused: zero + softmax stats (one pass) ==============
__global__ void pstats(const float* __restrict__ preds, int n) {
    __shared__ float sm[256], ss[256];
    unsigned th = g_thresh;
    float m = -FLT_MAX, s = 0.f;
    for (int i = blockIdx.x * blockDim.x + threadIdx.x; i < n; i += gridDim.x * blockDim.x) {
        float v = preds[i];
        float pm = (f2key(v) <= th) ? 0.0f : v;
        g_predsmod[i] = pm;
        if (pm > m) { s = s * expf(m - pm) + 1.f; m = pm; }
        else s += expf(pm - m);
    }
    sm[threadIdx.x] = m; ss[threadIdx.x] = s;
    __syncthreads();
    for (int st = 128; st; st >>= 1) {
        if (threadIdx.x < st) {
            float m2 = sm[threadIdx.x + st], s2 = ss[threadIdx.x + st];
            float mm = sm[threadIdx.x], sc = ss[threadIdx.x];
            msmerge(mm, sc, m2, s2);
            sm[threadIdx.x] = mm; ss[threadIdx.x] = sc;
        }
        __syncthreads();
    }
    if (threadIdx.x == 0) { g_pmax[blockIdx.x] = sm[0]; g_psum[blockIdx.x] = ss[0]; }
}
__global__ void pstats_fin() {
    __shared__ float sm[256], ss[256];
    sm[threadIdx.x] = g_pmax[threadIdx.x];
    ss[threadIdx.x] = g_psum[threadIdx.x];
    __syncthreads();
    for (int st = 128; st; st >>= 1) {
        if (threadIdx.x < st) {
            float mm = sm[threadIdx.x], sc = ss[threadIdx.x];
            msmerge(mm, sc, sm[threadIdx.x + st], ss[threadIdx.x + st]);
            sm[threadIdx.x] = mm; ss[threadIdx.x] = sc;
        }
        __syncthreads();
    }
    if (threadIdx.x == 0) { g_maxv = sm[0]; g_sumv = ss[0]; }
}
__global__ void scalek(int n) {
    float mx = g_maxv, sv = g_sumv;
    for (int i = blockIdx.x * blockDim.x + threadIdx.x; i < n; i += gridDim.x * blockDim.x)
        g_scale[i] = 1.0f + expf(g_predsmod[i] - mx) / sv;
}

// ======================= conversions (device-symbol writes only) =============
__global__ void convA(const float* __restrict__ feats, int n) {
    int total = n * DD;
    for (int i = blockIdx.x * blockDim.x + threadIdx.x; i < total; i += gridDim.x * blockDim.x) {
        int row = i >> 9;
        float v = feats[i] * g_scale[row];
        split2(v, g_fAh[i], g_fAl[i]);
    }
}
__global__ void convWlin(const float* __restrict__ W) {
    for (int i = blockIdx.x * blockDim.x + threadIdx.x; i < DD * DD; i += gridDim.x * blockDim.x)
        split2(W[i], g_Wlh[i], g_Wll[i]);
}
__global__ void convWq(const float* __restrict__ W) {
    for (int i = blockIdx.x * blockDim.x + threadIdx.x; i < QD * DD; i += gridDim.x * blockDim.x)
        split2(W[i], g_Wqh[i], g_Wql[i]);
}

// ======================= split-bf16 mma.sync GEMM, 512 threads ===============
// 16 warps (4x4), warp tile 32x32, acc[2][4][4]. Direct-LDS fragments (validated).
// MODE 0: f = relu((feats*scale)@Wlin^T + b) -> g_fh/g_fl  (grid 4 x rowTiles)
// MODE 2: Alog = tanh(f@Wq^T + bq) . qmax / sqrt128        (grid 1 x rowTiles)
template <int MODE>
__global__ void __launch_bounds__(512) mma_gemm(const float* __restrict__ bias, int n) {
    __shared__ __align__(16) char smc[4 * TILEB + 5632];
    const int tid = threadIdx.x;
    const int lane = tid & 31;
    const int wid = tid >> 5;      // 0..15
    const int wm = wid >> 2;       // 0..3 (32-row tile)
    const int wn = wid & 3;        // 0..3 (32-col tile)
    const int rowBase = blockIdx.y * 128;
    const int colBase = blockIdx.x * 128;

    const __nv_bfloat16* Ahp = (MODE == 0) ? g_fAh : g_fh;
    const __nv_bfloat16* Alp = (MODE == 0) ? g_fAl : g_fl;
    const __nv_bfloat16* Bhp = (MODE == 0) ? g_Wlh : g_Wqh;
    const __nv_bfloat16* Blp = (MODE == 0) ? g_Wll : g_Wql;

    float* qm0 = (float*)(smc + 4 * TILEB);
    float* qm1 = (float*)(smc + 4 * TILEB + 512);
    float* bsm = (float*)(smc + 4 * TILEB + 1024);
    float* red = (float*)(smc + 4 * TILEB + 1536);   // 128*4*2 floats

    if (MODE == 2 && tid < 128) {
        qm0[tid] = g_qmax[tid];
        qm1[tid] = g_qmax[128 + tid];
        bsm[tid] = bias[tid];
    }

    // staging: 2048 uint4 over 512 threads -> 4 each
    int pidx[4], prow[4], pchk[4];
    const __nv_bfloat16* psrc[4];
#pragma unroll
    for (int t = 0; t < 4; t++) {
        int idx = tid + t * 512;
        int tile = idx >> 9;           // 0 Ah, 1 Al, 2 Bh, 3 Bl
        int rem = idx & 511;
        int r = rem >> 2;
        int c = rem & 3;
        pidx[t] = tile; prow[t] = r; pchk[t] = c;
        if (tile < 2) {
            int row = rowBase + r;
            int rc = row < n ? row : 0;
            psrc[t] = (tile ? Alp : Ahp) + ((size_t)rc * DD + c * 8);
            if (row >= n) psrc[t] = nullptr;
        } else {
            int row = colBase + r;
            psrc[t] = (tile == 3 ? Blp : Bhp) + ((size_t)row * DD + c * 8);
        }
    }

    uint4 pf[4];
    auto ldg_stage = [&](int kt) {
#pragma unroll
        for (int t = 0; t < 4; t++) {
            if (psrc[t]) pf[t] = *(const uint4*)(psrc[t] + kt * 32);
            else pf[t] = make_uint4(0, 0, 0, 0);
        }
    };
    auto sts_stage = [&]() {
#pragma unroll
        for (int t = 0; t < 4; t++)
            *(uint4*)(smc + (pidx[t] * TILEB + prow[t] * TROW + pchk[t] * 16)) = pf[t];
    };

    float acc[2][4][4];
#pragma unroll
    for (int i = 0; i < 2; i++)
#pragma unroll
        for (int j = 0; j < 4; j++)
#pragma unroll
            for (int q = 0; q < 4; q++) acc[i][j][q] = 0.f;

    ldg_stage(0);
    for (int kt = 0; kt < 16; kt++) {
        __syncthreads();
        sts_stage();
        __syncthreads();
        if (kt < 15) ldg_stage(kt + 1);

#pragma unroll
        for (int ks = 0; ks < 2; ks++) {
            uint32_t ah[2][4], al[2][4];
            uint32_t bh[4][2], bl[4][2];
            const uint32_t kb = (uint32_t)(ks * 32 + (lane & 3) * 4);
            const uint32_t grow = (uint32_t)(lane >> 2);
#pragma unroll
            for (int mi = 0; mi < 2; mi++) {
                uint32_t ro0 = (uint32_t)(wm * 32 + mi * 16 + grow) * TROW + kb;
                uint32_t ro1 = ro0 + 8 * TROW;
                ah[mi][0] = *(const uint32_t*)(smc + ro0);
                ah[mi][1] = *(const uint32_t*)(smc + ro1);
                ah[mi][2] = *(const uint32_t*)(smc + ro0 + 16);
                ah[mi][3] = *(const uint32_t*)(smc + ro1 + 16);
                al[mi][0] = *(const uint32_t*)(smc + TILEB + ro0);
                al[mi][1] = *(const uint32_t*)(smc + TILEB + ro1);
                al[mi][2] = *(const uint32_t*)(smc + TILEB + ro0 + 16);
                al[mi][3] = *(const uint32_t*)(smc + TILEB + ro1 + 16);
            }
#pragma unroll
            for (int ni = 0; ni < 4; ni++) {
                uint32_t ro = (uint32_t)(wn * 32 + ni * 8 + grow) * TROW + kb;
                bh[ni][0] = *(const uint32_t*)(smc + 2 * TILEB + ro);
                bh[ni][1] = *(const uint32_t*)(smc + 2 * TILEB + ro + 16);
                bl[ni][0] = *(const uint32_t*)(smc + 3 * TILEB + ro);
                bl[ni][1] = *(const uint32_t*)(smc + 3 * TILEB + ro + 16);
            }
#pragma unroll
            for (int mi = 0; mi < 2; mi++)
#pragma unroll
                for (int ni = 0; ni < 4; ni++) {
                    mma16816(acc[mi][ni], ah[mi], bh[ni][0], bh[ni][1]);
                    mma16816(acc[mi][ni], ah[mi], bl[ni][0], bl[ni][1]);
                    mma16816(acc[mi][ni], al[mi], bh[ni][0], bh[ni][1]);
                }
        }
    }
    __syncthreads();

    if (MODE == 2) {
        float p[2][2][2];
#pragma unroll
        for (int mi = 0; mi < 2; mi++)
#pragma unroll
            for (int h = 0; h < 2; h++) { p[mi][h][0] = 0.f; p[mi][h][1] = 0.f; }
#pragma unroll
        for (int mi = 0; mi < 2; mi++)
#pragma unroll
            for (int ni = 0; ni < 4; ni++) {
                int cb = wn * 32 + ni * 8 + (lane & 3) * 2;
                float q00 = tanhf(acc[mi][ni][0] + bsm[cb]);
                float q01 = tanhf(acc[mi][ni][1] + bsm[cb + 1]);
                float q10 = tanhf(acc[mi][ni][2] + bsm[cb]);
                float q11 = tanhf(acc[mi][ni][3] + bsm[cb + 1]);
                p[mi][0][0] += q00 * qm0[cb] + q01 * qm0[cb + 1];
                p[mi][0][1] += q00 * qm1[cb] + q01 * qm1[cb + 1];
                p[mi][1][0] += q10 * qm0[cb] + q11 * qm0[cb + 1];
                p[mi][1][1] += q10 * qm1[cb] + q11 * qm1[cb + 1];
            }
#pragma unroll
        for (int mi = 0; mi < 2; mi++)
#pragma unroll
            for (int h = 0; h < 2; h++)
#pragma unroll
                for (int cc = 0; cc < 2; cc++) {
                    float v = p[mi][h][cc];
                    v += __shfl_xor_sync(0xffffffffu, v, 1);
                    v += __shfl_xor_sync(0xffffffffu, v, 2);
                    p[mi][h][cc] = v;
                }
        if ((lane & 3) == 0) {
#pragma unroll
            for (int mi = 0; mi < 2; mi++)
#pragma unroll
                for (int h = 0; h < 2; h++) {
                    int rloc = wm * 32 + mi * 16 + (lane >> 2) + h * 8;
                    red[(rloc * 4 + wn) * 2 + 0] = p[mi][h][0];
                    red[(rloc * 4 + wn) * 2 + 1] = p[mi][h][1];
                }
        }
        __syncthreads();
        if (tid < 128) {
            int row = rowBase + tid;
            if (row < n) {
                float s0 = 0.f, s1 = 0.f;
#pragma unroll
                for (int w = 0; w < 4; w++) {
                    s0 += red[(tid * 4 + w) * 2 + 0];
                    s1 += red[(tid * 4 + w) * 2 + 1];
                }
                g_Alog[(size_t)row * 2 + 0] = s0 * 0.08838834764831845f;
                g_Alog[(size_t)row * 2 + 1] = s1 * 0.08838834764831845f;
            }
        }
    } else {
#pragma unroll
        for (int mi = 0; mi < 2; mi++)
#pragma unroll
            for (int h = 0; h < 2; h++) {
                int row = rowBase + wm * 32 + mi * 16 + (lane >> 2) + h * 8;
                if (row < n) {
#pragma unroll
                    for (int ni = 0; ni < 4; ni++) {
                        int col = colBase + wn * 32 + ni * 8 + (lane & 3) * 2;
                        float v0 = fmaxf(acc[mi][ni][h * 2 + 0] + __ldg(&bias[col]), 0.f);
                        float v1 = fmaxf(acc[mi][ni][h * 2 + 1] + __ldg(&bias[col + 1]), 0.f);
                        size_t oidx = (size_t)row * DD + col;
                        __nv_bfloat16 h0, l0, h1, l1;
                        split2(v0, h0, l0);
                        split2(v1, h1, l1);
                        *(__nv_bfloat162*)(g_fh + oidx) = __nv_bfloat162(h0, h1);
                        *(__nv_bfloat162*)(g_fl + oidx) = __nv_bfloat162(l0, l1);
                    }
                }
            }
    }
}

// ======================= checkers =======================
__global__ void chk1(const float* __restrict__ feats, const float* __restrict__ W, int n) {
    int s = blockIdx.x * blockDim.x + threadIdx.x;
    int r = (s * 197 + 31) % n;
    int col = (s * 101 + 7) & 511;
    float sc = g_scale[r];
    const float* a = feats + (size_t)r * DD;
    const float* w = W + (size_t)col * DD;
    float acc = 0.f;
    for (int d = 0; d < DD; d++) acc = fmaf(a[d] * sc, w[d], acc);
    float ref = fmaxf(acc, 0.f);
    float got = fget((size_t)r * DD + col);
    if (fabsf(ref - got) > 5e-3f + 1e-3f * fabsf(ref)) g_bad[0] = 1;
}
__global__ void chkQ(const float* __restrict__ Wq, const float* __restrict__ bq, int n) {
    __shared__ float s0[128], s1[128];
    int s = blockIdx.x;
    int j = threadIdx.x;
    int r = (s * 1579 + 131) % n;
    const float* w = Wq + (size_t)j * DD;
    float acc = 0.f;
    for (int d = 0; d < DD; d++) acc = fmaf(fget((size_t)r * DD + d), w[d], acc);
    float q = tanhf(acc + bq[j]);
    s0[j] = q * g_qmax[j];
    s1[j] = q * g_qmax[QD + j];
    __syncthreads();
    for (int st = 64; st; st >>= 1) {
        if (j < st) { s0[j] += s0[j + st]; s1[j] += s1[j + st]; }
        __syncthreads();
    }
    if (j == 0) {
        float r0 = s0[0] * 0.08838834764831845f;
        float r1 = s1[0] * 0.08838834764831845f;
        if (fabsf(r0 - g_Alog[(size_t)r * 2 + 0]) > 5e-3f + 1e-3f * fabsf(r0)) g_bad[2] = 1;
        if (fabsf(r1 - g_Alog[(size_t)r * 2 + 1]) > 5e-3f + 1e-3f * fabsf(r1)) g_bad[2] = 1;
    }
}

// ======================= FFMA fallback GEMMs (proven; gated) =================
__global__ void __launch_bounds__(256) fgemm0(const float* __restrict__ Aext,
                                              const float* __restrict__ W,
                                              const float* __restrict__ bias, int n) {
    if (g_bad[0] == 0) return;
    __shared__ float As[8][128];
    __shared__ float Ws[8][128];
    int tid = threadIdx.x;
    int ty = tid >> 4, tx = tid & 15;
    int rowBase = blockIdx.x * 128;
    int colBase = blockIdx.y * 128;
    float acc[8][8];
#pragma unroll
    for (int i = 0; i < 8; i++)
#pragma unroll
        for (int j = 0; j < 8; j++) acc[i][j] = 0.f;

    int ml = tid >> 1;
    int kq = (tid & 1) * 4;
    int arow = rowBase + ml;
    bool avalid = arow < n;
    float sc = avalid ? g_scale[arow] : 1.f;
    const float* Aptr = Aext + (avalid ? (size_t)arow * DD : 0);
    const float* Wptr = W + (size_t)(colBase + ml) * DD;

    for (int kt = 0; kt < DD; kt += 8) {
        float4 av = make_float4(0.f, 0.f, 0.f, 0.f);
        if (avalid) {
            av = *(const float4*)(Aptr + kt + kq);
            av.x *= sc; av.y *= sc; av.z *= sc; av.w *= sc;
        }
        As[kq + 0][ml] = av.x; As[kq + 1][ml] = av.y;
        As[kq + 2][ml] = av.z; As[kq + 3][ml] = av.w;
        float4 wv = *(const float4*)(Wptr + kt + kq);
        Ws[kq + 0][ml] = wv.x; Ws[kq + 1][ml] = wv.y;
        Ws[kq + 2][ml] = wv.z; Ws[kq + 3][ml] = wv.w;
        __syncthreads();
#pragma unroll
        for (int kk = 0; kk < 8; kk++) {
            float a[8], b[8];
            const float4* Ap = (const float4*)&As[kk][ty * 8];
            const float4* Bp = (const float4*)&Ws[kk][tx * 8];
            float4 a0 = Ap[0], a1 = Ap[1];
            float4 b0 = Bp[0], b1 = Bp[1];
            a[0] = a0.x; a[1] = a0.y; a[2] = a0.z; a[3] = a0.w;
            a[4] = a1.x; a[5] = a1.y; a[6] = a1.z; a[7] = a1.w;
            b[0] = b0.x; b[1] = b0.y; b[2] = b0.z; b[3] = b0.w;
            b[4] = b1.x; b[5] = b1.y; b[6] = b1.z; b[7] = b1.w;
#pragma unroll
            for (int i = 0; i < 8; i++)
#pragma unroll
                for (int j = 0; j < 8; j++) acc[i][j] = fmaf(a[i], b[j], acc[i][j]);
        }
        __syncthreads();
    }
#pragma unroll
    for (int i = 0; i < 8; i++) {
        int r = rowBase + ty * 8 + i;
        if (r >= n) continue;
#pragma unroll
        for (int j = 0; j < 8; j++) {
            int o = colBase + tx * 8 + j;
            float v = fmaxf(acc[i][j] + bias[o], 0.f);
            size_t oidx = (size_t)r * DD + o;
            split2(v, g_fh[oidx], g_fl[oidx]);
        }
    }
}

__global__ void __launch_bounds__(256) fgemmq(const float* __restrict__ Wq,
                                              const float* __restrict__ bq, int n) {
    if (g_bad[2] == 0) return;
    __shared__ float As[8][128];
    __shared__ float Ws[8][128];
    __shared__ float pA[2][16][8][16];
    int tid = threadIdx.x;
    int ty = tid >> 4, tx = tid & 15;
    int rowBase = blockIdx.x * 128;
    float acc[8][8];
#pragma unroll
    for (int i = 0; i < 8; i++)
#pragma unroll
        for (int j = 0; j < 8; j++) acc[i][j] = 0.f;

    int ml = tid >> 1;
    int kq = (tid & 1) * 4;
    int arow = rowBase + ml;
    bool avalid = arow < n;
    const size_t foff = avalid ? (size_t)arow * DD : 0;
    const float* Wptr = Wq + (size_t)ml * DD;

    for (int kt = 0; kt < DD; kt += 8) {
        float4 av = make_float4(0.f, 0.f, 0.f, 0.f);
        if (avalid) {
            size_t o = foff + kt + kq;
            av.x = fget(o); av.y = fget(o + 1); av.z = fget(o + 2); av.w = fget(o + 3);
        }
        As[kq + 0][ml] = av.x; As[kq + 1][ml] = av.y;
        As[kq + 2][ml] = av.z; As[kq + 3][ml] = av.w;
        float4 wv = *(const float4*)(Wptr + kt + kq);
        Ws[kq + 0][ml] = wv.x; Ws[kq + 1][ml] = wv.y;
        Ws[kq + 2][ml] = wv.z; Ws[kq + 3][ml] = wv.w;
        __syncthreads();
#pragma unroll
        for (int kk = 0; kk < 8; kk++) {
            float a[8], b[8];
            const float4* Ap = (const float4*)&As[kk][ty * 8];
            const float4* Bp = (const float4*)&Ws[kk][tx * 8];
            float4 a0 = Ap[0], a1 = Ap[1];
            float4 b0 = Bp[0], b1 = Bp[1];
            a[0] = a0.x; a[1] = a0.y; a[2] = a0.z; a[3] = a0.w;
            a[4] = a1.x; a[5] = a1.y; a[6] = a1.z; a[7] = a1.w;
            b[0] = b0.x; b[1] = b0.y; b[2] = b0.z; b[3] = b0.w;
            b[4] = b1.x; b[5] = b1.y; b[6] = b1.z; b[7] = b1.w;
#pragma unroll
            for (int i = 0; i < 8; i++)
#pragma unroll
                for (int j = 0; j < 8; j++) acc[i][j] = fmaf(a[i], b[j], acc[i][j]);
        }
        __syncthreads();
    }

    float p0[8], p1[8];
#pragma unroll
    for (int i = 0; i < 8; i++) { p0[i] = 0.f; p1[i] = 0.f; }
#pragma unroll
    for (int j = 0; j < 8; j++) {
        int o = tx * 8 + j;
        float qm0 = g_qmax[o];
        float qm1 = g_qmax[QD + o];
        float bqo = bq[o];
#pragma unroll
        for (int i = 0; i < 8; i++) {
            float q = tanhf(acc[i][j] + bqo);
            p0[i] = fmaf(q, qm0, p0[i]);
            p1[i] = fmaf(q, qm1, p1[i]);
        }
    }
#pragma unroll
    for (int i = 0; i < 8; i++) {
        pA[0][ty][i][tx] = p0[i];
        pA[1][ty][i][tx] = p1[i];
    }
    __syncthreads();
    int cc = tid >> 7;
    int rem = tid & 127;
    int tyy = rem >> 3, ii = rem & 7;
    float s = 0.f;
#pragma unroll
    for (int t = 0; t < 16; t++) s += pA[cc][tyy][ii][t];
    int r = rowBase + tyy * 8 + ii;
    if (r < n) g_Alog[(size_t)r * 2 + cc] = s * 0.08838834764831845f;
}

// ======================= argmax over c columns =======================
__global__ void cargpart(const float* __restrict__ c, int n) {
    __shared__ float sv[256][2];
    __shared__ int si[256][2];
    float bv0 = -FLT_MAX, bv1 = -FLT_MAX;
    int bi0 = 0x7fffffff, bi1 = 0x7fffffff;
    for (int i = blockIdx.x * blockDim.x + threadIdx.x; i < n; i += gridDim.x * blockDim.x) {
        float v0 = c[(size_t)i * 2];
        float v1 = c[(size_t)i * 2 + 1];
        if (v0 > bv0 || (v0 == bv0 && i < bi0)) { bv0 = v0; bi0 = i; }
        if (v1 > bv1 || (v1 == bv1 && i < bi1)) { bv1 = v1; bi1 = i; }
    }
    sv[threadIdx.x][0] = bv0; si[threadIdx.x][0] = bi0;
    sv[threadIdx.x][1] = bv1; si[threadIdx.x][1] = bi1;
    __syncthreads();
    for (int st = 128; st; st >>= 1) {
        if (threadIdx.x < st) {
#pragma unroll
            for (int cc = 0; cc < 2; cc++) {
                float v = sv[threadIdx.x + st][cc];
                int ii = si[threadIdx.x + st][cc];
                if (v > sv[threadIdx.x][cc] ||
                    (v == sv[threadIdx.x][cc] && ii < si[threadIdx.x][cc])) {
                    sv[threadIdx.x][cc] = v;
                    si[threadIdx.x][cc] = ii;
                }
            }
        }
        __syncthreads();
    }
    if (threadIdx.x == 0) {
        g_cpv[blockIdx.x * 2 + 0] = sv[0][0]; g_cpi[blockIdx.x * 2 + 0] = si[0][0];
        g_cpv[blockIdx.x * 2 + 1] = sv[0][1]; g_cpi[blockIdx.x * 2 + 1] = si[0][1];
    }
}
__global__ void cargfin() {
    int cc = threadIdx.x;
    if (cc < 2) {
        float bv = -FLT_MAX;
        int bi = 0x7fffffff;
        for (int b = 0; b < 128; b++) {
            float v = g_cpv[b * 2 + cc];
            int ii = g_cpi[b * 2 + cc];
            if (v > bv || (v == bv && ii < bi)) { bv = v; bi = ii; }
        }
        g_midx[cc] = bi;
    }
}

// ======================= q_max rows =======================
__global__ void qmaxk(const float* __restrict__ Wq, const float* __restrict__ bq) {
    int t = threadIdx.x;
    int cls = t >> 7, j = t & 127;
    const size_t r = (size_t)g_midx[cls] * DD;
    const float* wrow = Wq + (size_t)j * DD;
    float s = 0.f;
    for (int d = 0; d < DD; d++) s = fmaf(fget(r + d), wrow[d], s);
    g_qmax[cls * QD + j] = tanhf(s + bq[j]);
}

// ======================= fused A-softmax stats =======================
__global__ void astats(int n) {
    __shared__ float sm0[256], ss0[256], sm1[256], ss1[256];
    float m0 = -FLT_MAX, s0 = 0.f, m1 = -FLT_MAX, s1 = 0.f;
    for (int i = blockIdx.x * blockDim.x + threadIdx.x; i < n; i += gridDim.x * blockDim.x) {
        float v0 = g_Alog[(size_t)i * 2];
        float v1 = g_Alog[(size_t)i * 2 + 1];
        if (v0 > m0) { s0 = s0 * expf(m0 - v0) + 1.f; m0 = v0; } else s0 += expf(v0 - m0);
        if (v1 > m1) { s1 = s1 * expf(m1 - v1) + 1.f; m1 = v1; } else s1 += expf(v1 - m1);
    }
    sm0[threadIdx.x] = m0; ss0[threadIdx.x] = s0;
    sm1[threadIdx.x] = m1; ss1[threadIdx.x] = s1;
    __syncthreads();
    for (int st = 128; st; st >>= 1) {
        if (threadIdx.x < st) {
            float mm = sm0[threadIdx.x], sc = ss0[threadIdx.x];
            msmerge(mm, sc, sm0[threadIdx.x + st], ss0[threadIdx.x + st]);
            sm0[threadIdx.x] = mm; ss0[threadIdx.x] = sc;
            mm = sm1[threadIdx.x]; sc = ss1[threadIdx.x];
            msmerge(mm, sc, sm1[threadIdx.x + st], ss1[threadIdx.x + st]);
            sm1[threadIdx.x] = mm; ss1[threadIdx.x] = sc;
        }
        __syncthreads();
    }
    if (threadIdx.x == 0) {
        g_apm[blockIdx.x * 2 + 0] = sm0[0]; g_aps[blockIdx.x * 2 + 0] = ss0[0];
        g_apm[blockIdx.x * 2 + 1] = sm1[0]; g_aps[blockIdx.x * 2 + 1] = ss1[0];
    }
}
__global__ void astats_fin() {
    if (threadIdx.x < 2) {
        int cc = threadIdx.x;
        float m = -FLT_MAX, s = 0.f;
        for (int b = 0; b < 256; b++) msmerge(m, s, g_apm[b * 2 + cc], g_aps[b * 2 + cc]);
        g_amax[cc] = m;
        g_asum[cc] = s;
    }
}
__global__ void anorm(float* __restrict__ out, int n) {
    float m0 = g_amax[0], m1 = g_amax[1];
    float r0 = 1.0f / g_asum[0], r1 = 1.0f / g_asum[1];
    for (int i = blockIdx.x * blockDim.x + threadIdx.x; i < n; i += gridDim.x * blockDim.x) {
        out[2 + (size_t)i * 2] = expf(g_Alog[(size_t)i * 2] - m0) * r0;
        out[2 + (size_t)i * 2 + 1] = expf(g_Alog[(size_t)i * 2 + 1] - m1) * r1;
    }
}

// ======================= T = A^T @ f ; B = T @ Wv^T + bv =======================
__global__ void bpartF(const float* __restrict__ out, int n) {
    int b = blockIdx.x;
    int col = threadIdx.x; // 512
    int chunk = (n + gridDim.x - 1) / gridDim.x;
    int r0 = b * chunk;
    int r1 = min(n, r0 + chunk);
    float a0 = 0.f, a1 = 0.f;
    const float* Aout = out + 2;
    for (int r = r0; r < r1; r++) {
        float A0 = Aout[(size_t)r * 2];
        float A1 = Aout[(size_t)r * 2 + 1];
        float v = fget((size_t)r * DD + col);
        a0 = fmaf(A0, v, a0);
        a1 = fmaf(A1, v, a1);
    }
    g_Bpart[(b * 2 + 0) * DD + col] = a0;
    g_Bpart[(b * 2 + 1) * DD + col] = a1;
}
__global__ void tfin() {
    int col = threadIdx.x; // 512
    float a0 = 0.f, a1 = 0.f;
    for (int b = 0; b < BBLK; b++) {
        a0 += g_Bpart[(b * 2 + 0) * DD + col];
        a1 += g_Bpart[(b * 2 + 1) * DD + col];
    }
    g_T[col] = a0;
    g_T[DD + col] = a1;
}
__global__ void bmm(const float* __restrict__ Wv, const float* __restrict__ bv,
                    float* __restrict__ out, int n) {
    int j = blockIdx.x * blockDim.x + threadIdx.x;  // <<<2,256>>>
    if (j >= DD) return;
    const float* w = Wv + (size_t)j * DD;
    float a0 = 0.f, a1 = 0.f;
    for (int d = 0; d < DD; d++) {
        float wv = w[d];
        a0 = fmaf(g_T[d], wv, a0);
        a1 = fmaf(g_T[DD + d], wv, a1);
    }
    a0 += bv[j];
    a1 += bv[j];
    g_B[j] = a0;
    g_B[DD + j] = a1;
    size_t off = 2 + (size_t)2 * n;
    out[off + j] = a0;
    out[off + DD + j] = a1;
}

// ======================= Cout =======================
__global__ void coutk(const float* __restrict__ Wf, const float* __restrict__ bf,
                      float* __restrict__ out) {
    __shared__ float s0[256], s1[256];
    int t = threadIdx.x;
    float a0 = 0.f, a1 = 0.f;
    for (int idx = t; idx < 1024; idx += 256) {
        float b = g_B[idx];
        a0 = fmaf(b, Wf[idx], a0);
        a1 = fmaf(b, Wf[1024 + idx], a1);
    }
    s0[t] = a0; s1[t] = a1;
    __syncthreads();
    for (int st = 128; st; st >>= 1) {
        if (t < st) { s0[t] += s0[t + st]; s1[t] += s1[t + st]; }
        __syncthreads();
    }
    if (t == 0) {
        out[0] = s0[0] + bf[0];
        out[1] = s1[0] + bf[1];
    }
}

// ======================= launch =======================
extern "C" void kernel_launch(void* const* d_in, const int* in_sizes, int n_in,
                              void* d_out, int out_size) {
    const float* feats = (const float*)d_in[0];
    const float* c     = (const float*)d_in[1];
    const float* sp    = (const float*)d_in[2];
    const float* Wlin  = (const float*)d_in[3];
    const float* blin  = (const float*)d_in[4];
    const float* Wq    = (const float*)d_in[5];
    const float* bq    = (const float*)d_in[6];
    const float* Wv    = (const float*)d_in[7];
    const float* bv    = (const float*)d_in[8];
    const float* Wf    = (const float*)d_in[9];
    const float* bf    = (const float*)d_in[10];
    float* out = (float*)d_out;

    int n = in_sizes[2];
    int k = (int)(0.2 * (double)n);
    int rowTiles = (n + 127) / 128;

    // 1) bottom-k select (resets g_bad)
    init_sel<<<1, 256>>>(k);
    for (int p = 0; p < 4; p++) {
        hist_kernel<<<256, 256>>>(sp, n, p);
        scan_kernel<<<1, 256>>>(p);
    }

    // 2) fused zero + instance-softmax stats -> scale
    pstats<<<256, 256>>>(sp, n);
    pstats_fin<<<1, 256>>>();
    scalek<<<256, 256>>>(n);

    // 3) conversions (device-symbol writes only)
    convWlin<<<256, 256>>>(Wlin);
    convWq<<<64, 256>>>(Wq);
    convA<<<2048, 256>>>(feats, n);

    // 4) f GEMM: split-bf16 MMA (512-thread), verify, gated FFMA fallback
    mma_gemm<0><<<dim3(4, rowTiles), 512>>>(blin, n);
    chk1<<<4, 128>>>(feats, Wlin, n);
    fgemm0<<<dim3(rowTiles, 4), 256>>>(feats, Wlin, blin, n);

    // 5) critical instances and q_max
    cargpart<<<128, 256>>>(c, n);
    cargfin<<<1, 32>>>();
    qmaxk<<<1, 256>>>(Wq, bq);

    // 6) Q GEMM + A logits: split-bf16 MMA (512-thread), verify, fallback
    mma_gemm<2><<<dim3(1, rowTiles), 512>>>(bq, n);
    chkQ<<<64, 128>>>(Wq, bq, n);
    fgemmq<<<rowTiles, 256>>>(Wq, bq, n);

    // 7) fused column-softmax stats + normalize -> out[2 : 2+2n]
    astats<<<256, 256>>>(n);
    astats_fin<<<1, 32>>>();
    anorm<<<256, 256>>>(out, n);

    // 8) B = (A^T @ f) @ Wv^T + bv   (V GEMM eliminated)
    bpartF<<<BBLK, 512>>>(out, n);
    tfin<<<1, 512>>>();
    bmm<<<2, 256>>>(Wv, bv, out, n);

    // 9) Cout
    coutk<<<1, 256>>>(Wf, bf, out);
}

// round 17
// speedup vs baseline: 1.1302x; 1.1302x over previous
#include <cuda_runtime.h>
#include <cuda_bf16.h>
#include <math.h>
#include <float.h>
#include <stdint.h>

#define NMAX 100000
#define DD 512
#define QD 128
#define BBLK 64
#define TROW 80
#define TILEB 10240

// ======================= helpers =======================
__device__ __forceinline__ uint32_t smem_u32(const void* p) {
    uint32_t a;
    asm("{ .reg .u64 t; cvta.to.shared.u64 t, %1; cvt.u32.u64 %0, t; }" : "=r"(a) : "l"(p));
    return a;
}
__device__ __forceinline__ void mma16816(float (&c)[4], const uint32_t (&a)[4],
                                         uint32_t b0, uint32_t b1) {
    asm volatile(
        "mma.sync.aligned.m16n8k16.row.col.f32.bf16.bf16.f32 "
        "{%0,%1,%2,%3}, {%4,%5,%6,%7}, {%8,%9}, {%0,%1,%2,%3};"
        : "+f"(c[0]), "+f"(c[1]), "+f"(c[2]), "+f"(c[3])
        : "r"(a[0]), "r"(a[1]), "r"(a[2]), "r"(a[3]), "r"(b0), "r"(b1));
}
__device__ __forceinline__ void cpasync16(uint32_t dst, const void* src, int sb) {
    asm volatile("cp.async.cg.shared.global [%0], [%1], 16, %2;"
                 :: "r"(dst), "l"(src), "r"(sb) : "memory");
}
#define CP_COMMIT() asm volatile("cp.async.commit_group;" ::: "memory")
#define CP_WAIT0() asm volatile("cp.async.wait_group 0;" ::: "memory")

// ======================= scratch (device symbols; never passed from host) ====
static __device__ float g_predsmod[NMAX];
static __device__ float g_scale[NMAX];
static __device__ __align__(16) __nv_bfloat16 g_fAh[(size_t)NMAX * DD];
static __device__ __align__(16) __nv_bfloat16 g_fAl[(size_t)NMAX * DD];
static __device__ __align__(16) __nv_bfloat16 g_fh[(size_t)NMAX * DD];
static __device__ __align__(16) __nv_bfloat16 g_fl[(size_t)NMAX * DD];
static __device__ float g_Alog[(size_t)NMAX * 2];
static __device__ __align__(16) __nv_bfloat16 g_Wlh[DD * DD], g_Wll[DD * DD];
static __device__ __align__(16) __nv_bfloat16 g_Wqh[QD * DD], g_Wql[QD * DD];

static __device__ int g_bad[3];

static __device__ unsigned g_hist[256];
static __device__ unsigned g_prefix;
static __device__ int g_krem;
static __device__ unsigned g_thresh;
static __device__ float g_pmax[256];
static __device__ float g_psum[256];
static __device__ float g_maxv;
static __device__ float g_sumv;
static __device__ float g_cpv[128 * 2];
static __device__ int g_cpi[128 * 2];
static __device__ int g_midx[2];
static __device__ float g_qmax[2 * QD];
static __device__ float g_apm[256 * 2];
static __device__ float g_aps[256 * 2];
static __device__ float g_amax[2];
static __device__ float g_asum[2];
static __device__ float g_Bpart[BBLK * 2 * DD];
static __device__ float g_T[2 * DD];
static __device__ float g_B[2 * DD];

static __device__ __forceinline__ unsigned f2key(float x) {
    unsigned u = __float_as_uint(x);
    return (u & 0x80000000u) ? ~u : (u | 0x80000000u);
}
static __device__ __forceinline__ void split2(float v, __nv_bfloat16& h, __nv_bfloat16& l) {
    h = __float2bfloat16(v);
    l = __float2bfloat16(v - __bfloat162float(h));
}
static __device__ __forceinline__ float fget(size_t idx) {
    return __bfloat162float(g_fh[idx]) + __bfloat162float(g_fl[idx]);
}
static __device__ __forceinline__ void msmerge(float& m, float& s, float m2, float s2) {
    if (m2 > m) { s = s * expf(m - m2) + s2; m = m2; }
    else if (m2 > -FLT_MAX) { s = s + s2 * expf(m2 - m); }
}

// ======================= radix select =======================
__global__ void init_sel(int k) {
    g_hist[threadIdx.x] = 0u;
    if (threadIdx.x < 3) g_bad[threadIdx.x] = 0;
    if (threadIdx.x == 0) { g_prefix = 0u; g_krem = k; }
}
__global__ void hist_kernel(const float* __restrict__ preds, int n, int p) {
    __shared__ unsigned sh[256];
    sh[threadIdx.x] = 0u;
    __syncthreads();
    int shift = 24 - 8 * p;
    unsigned pref = g_prefix;
    for (int i = blockIdx.x * blockDim.x + threadIdx.x; i < n; i += gridDim.x * blockDim.x) {
        unsigned key = f2key(preds[i]);
        bool m = (p == 0) || ((key >> (shift + 8)) == pref);
        if (m) atomicAdd(&sh[(key >> shift) & 255u], 1u);
    }
    __syncthreads();
    if (sh[threadIdx.x]) atomicAdd(&g_hist[threadIdx.x], sh[threadIdx.x]);
}
__global__ void scan_kernel(int p) {
    if (threadIdx.x == 0) {
        int krem = g_krem;
        unsigned cum = 0;
        int b = 0;
        for (b = 0; b < 256; b++) {
            unsigned h = g_hist[b];
            if (cum + h >= (unsigned)krem) break;
            cum += h;
        }
        g_prefix = (g_prefix << 8) | (unsigned)b;
        g_krem = krem - (int)cum;
        if (p == 3) g_thresh = g_prefix;
    }
    __syncthreads();
    g_hist[threadIdx.x] = 0u;
}

// ======================= fused zero + softmax stats ==========================
__global__ void pstats(const float* __restrict__ preds, int n) {
    __shared__ float sm[256], ss[256];
    unsigned th = g_thresh;
    float m = -FLT_MAX, s = 0.f;
    for (int i = blockIdx.x * blockDim.x + threadIdx.x; i < n; i += gridDim.x * blockDim.x) {
        float v = preds[i];
        float pm = (f2key(v) <= th) ? 0.0f : v;
        g_predsmod[i] = pm;
        if (pm > m) { s = s * expf(m - pm) + 1.f; m = pm; }
        else s += expf(pm - m);
    }
    sm[threadIdx.x] = m; ss[threadIdx.x] = s;
    __syncthreads();
    for (int st = 128; st; st >>= 1) {
        if (threadIdx.x < st) {
            float mm = sm[threadIdx.x], sc = ss[threadIdx.x];
            msmerge(mm, sc, sm[threadIdx.x + st], ss[threadIdx.x + st]);
            sm[threadIdx.x] = mm; ss[threadIdx.x] = sc;
        }
        __syncthreads();
    }
    if (threadIdx.x == 0) { g_pmax[blockIdx.x] = sm[0]; g_psum[blockIdx.x] = ss[0]; }
}
__global__ void pstats_fin() {
    __shared__ float sm[256], ss[256];
    sm[threadIdx.x] = g_pmax[threadIdx.x];
    ss[threadIdx.x] = g_psum[threadIdx.x];
    __syncthreads();
    for (int st = 128; st; st >>= 1) {
        if (threadIdx.x < st) {
            float mm = sm[threadIdx.x], sc = ss[threadIdx.x];
            msmerge(mm, sc, sm[threadIdx.x + st], ss[threadIdx.x + st]);
            sm[threadIdx.x] = mm; ss[threadIdx.x] = sc;
        }
        __syncthreads();
    }
    if (threadIdx.x == 0) { g_maxv = sm[0]; g_sumv = ss[0]; }
}
__global__ void scalek(int n) {
    float mx = g_maxv, sv = g_sumv;
    for (int i = blockIdx.x * blockDim.x + threadIdx.x; i < n; i += gridDim.x * blockDim.x)
        g_scale[i] = 1.0f + expf(g_predsmod[i] - mx) / sv;
}

// ======================= conversions =======================
__global__ void convA(const float* __restrict__ feats, int n) {
    int total = n * DD;
    for (int i = blockIdx.x * blockDim.x + threadIdx.x; i < total; i += gridDim.x * blockDim.x) {
        int row = i >> 9;
        float v = feats[i] * g_scale[row];
        split2(v, g_fAh[i], g_fAl[i]);
    }
}
__global__ void convWlin(const float* __restrict__ W) {
    for (int i = blockIdx.x * blockDim.x + threadIdx.x; i < DD * DD; i += gridDim.x * blockDim.x)
        split2(W[i], g_Wlh[i], g_Wll[i]);
}
__global__ void convWq(const float* __restrict__ W) {
    for (int i = blockIdx.x * blockDim.x + threadIdx.x; i < QD * DD; i += gridDim.x * blockDim.x)
        split2(W[i], g_Wqh[i], g_Wql[i]);
}

// ======================= split-bf16 mma.sync GEMM, 128 threads ===============
// 4 warps (2x2), warp tile 64x64, acc[4][8][4]. cp.async staging, TROW-80 layout.
// MODE 0: f = relu((feats*scale)@Wlin^T + b) -> g_fh/g_fl  (grid 4 x rowTiles)
// MODE 2: Alog = tanh(f@Wq^T + bq) . qmax / sqrt128        (grid 1 x rowTiles)
template <int MODE>
__global__ void __launch_bounds__(128) mma_gemm(const float* __restrict__ bias, int n) {
    __shared__ __align__(16) char smc[4 * TILEB + 5632];
    const uint32_t smemBase = smem_u32(smc);
    const int tid = threadIdx.x;
    const int lane = tid & 31;
    const int wid = tid >> 5;     // 0..3
    const int wm = wid >> 1;      // 0..1 (64-row tile)
    const int wn = wid & 1;       // 0..1 (64-col tile)
    const int rowBase = blockIdx.y * 128;
    const int colBase = blockIdx.x * 128;

    const __nv_bfloat16* Ahp = (MODE == 0) ? g_fAh : g_fh;
    const __nv_bfloat16* Alp = (MODE == 0) ? g_fAl : g_fl;
    const __nv_bfloat16* Bhp = (MODE == 0) ? g_Wlh : g_Wqh;
    const __nv_bfloat16* Blp = (MODE == 0) ? g_Wll : g_Wql;

    float* qm0 = (float*)(smc + 4 * TILEB);
    float* qm1 = (float*)(smc + 4 * TILEB + 512);
    float* bsm = (float*)(smc + 4 * TILEB + 1024);
    float* red = (float*)(smc + 4 * TILEB + 1536);   // 128*2*2 floats = 2KB

    if (MODE == 2) {
        qm0[tid] = g_qmax[tid];
        qm1[tid] = g_qmax[128 + tid];
        bsm[tid] = bias[tid];
    }

    // staging: 2048 x 16B over 128 threads -> 16 each (tile, row, chunk)
    uint32_t pdst[16];
    const __nv_bfloat16* psrc[16];
    int psb[16];
#pragma unroll
    for (int t = 0; t < 16; t++) {
        int idx = tid + t * 128;
        int tile = idx >> 9;          // 0 Ah, 1 Al, 2 Bh, 3 Bl
        int rem = idx & 511;
        int r = rem >> 2;
        int c = rem & 3;
        pdst[t] = smemBase + (uint32_t)(tile * TILEB + r * TROW + c * 16);
        if (tile < 2) {
            int row = rowBase + r;
            int rc = row < n ? row : 0;
            psrc[t] = (tile ? Alp : Ahp) + ((size_t)rc * DD + c * 8);
            psb[t] = (row < n) ? 16 : 0;
        } else {
            int row = colBase + r;
            psrc[t] = (tile == 3 ? Blp : Bhp) + ((size_t)row * DD + c * 8);
            psb[t] = 16;
        }
    }

    float acc[4][8][4];
#pragma unroll
    for (int i = 0; i < 4; i++)
#pragma unroll
        for (int j = 0; j < 8; j++)
#pragma unroll
            for (int q = 0; q < 4; q++) acc[i][j][q] = 0.f;

    for (int kt = 0; kt < 16; kt++) {
        __syncthreads();   // previous compute done reading smem
#pragma unroll
        for (int t = 0; t < 16; t++) cpasync16(pdst[t], psrc[t] + kt * 32, psb[t]);
        CP_COMMIT();
        CP_WAIT0();
        __syncthreads();   // staging visible to all

#pragma unroll
        for (int ks = 0; ks < 2; ks++) {
            uint32_t ah[4][4], al[4][4];
            uint32_t bh[8][2], bl[8][2];
            const uint32_t kb = (uint32_t)(ks * 32 + (lane & 3) * 4);
            const uint32_t grow = (uint32_t)(lane >> 2);
#pragma unroll
            for (int mi = 0; mi < 4; mi++) {
                uint32_t ro0 = (uint32_t)(wm * 64 + mi * 16 + grow) * TROW + kb;
                uint32_t ro1 = ro0 + 8 * TROW;
                ah[mi][0] = *(const uint32_t*)(smc + ro0);
                ah[mi][1] = *(const uint32_t*)(smc + ro1);
                ah[mi][2] = *(const uint32_t*)(smc + ro0 + 16);
                ah[mi][3] = *(const uint32_t*)(smc + ro1 + 16);
                al[mi][0] = *(const uint32_t*)(smc + TILEB + ro0);
                al[mi][1] = *(const uint32_t*)(smc + TILEB + ro1);
                al[mi][2] = *(const uint32_t*)(smc + TILEB + ro0 + 16);
                al[mi][3] = *(const uint32_t*)(smc + TILEB + ro1 + 16);
            }
#pragma unroll
            for (int ni = 0; ni < 8; ni++) {
                uint32_t ro = (uint32_t)(wn * 64 + ni * 8 + grow) * TROW + kb;
                bh[ni][0] = *(const uint32_t*)(smc + 2 * TILEB + ro);
                bh[ni][1] = *(const uint32_t*)(smc + 2 * TILEB + ro + 16);
                bl[ni][0] = *(const uint32_t*)(smc + 3 * TILEB + ro);
                bl[ni][1] = *(const uint32_t*)(smc + 3 * TILEB + ro + 16);
            }
#pragma unroll
            for (int mi = 0; mi < 4; mi++)
#pragma unroll
                for (int ni = 0; ni < 8; ni++) {
                    mma16816(acc[mi][ni], ah[mi], bh[ni][0], bh[ni][1]);
                    mma16816(acc[mi][ni], ah[mi], bl[ni][0], bl[ni][1]);
                    mma16816(acc[mi][ni], al[mi], bh[ni][0], bh[ni][1]);
                }
        }
    }
    __syncthreads();

    if (MODE == 2) {
        float p[4][2][2];
#pragma unroll
        for (int mi = 0; mi < 4; mi++)
#pragma unroll
            for (int h = 0; h < 2; h++) { p[mi][h][0] = 0.f; p[mi][h][1] = 0.f; }
#pragma unroll
        for (int mi = 0; mi < 4; mi++)
#pragma unroll
            for (int ni = 0; ni < 8; ni++) {
                int cb = wn * 64 + ni * 8 + (lane & 3) * 2;
                float q00 = tanhf(acc[mi][ni][0] + bsm[cb]);
                float q01 = tanhf(acc[mi][ni][1] + bsm[cb + 1]);
                float q10 = tanhf(acc[mi][ni][2] + bsm[cb]);
                float q11 = tanhf(acc[mi][ni][3] + bsm[cb + 1]);
                p[mi][0][0] += q00 * qm0[cb] + q01 * qm0[cb + 1];
                p[mi][0][1] += q00 * qm1[cb] + q01 * qm1[cb + 1];
                p[mi][1][0] += q10 * qm0[cb] + q11 * qm0[cb + 1];
                p[mi][1][1] += q10 * qm1[cb] + q11 * qm1[cb + 1];
            }
#pragma unroll
        for (int mi = 0; mi < 4; mi++)
#pragma unroll
            for (int h = 0; h < 2; h++)
#pragma unroll
                for (int cc = 0; cc < 2; cc++) {
                    float v = p[mi][h][cc];
                    v += __shfl_xor_sync(0xffffffffu, v, 1);
                    v += __shfl_xor_sync(0xffffffffu, v, 2);
                    p[mi][h][cc] = v;
                }
        if ((lane & 3) == 0) {
#pragma unroll
            for (int mi = 0; mi < 4; mi++)
#pragma unroll
                for (int h = 0; h < 2; h++) {
                    int rloc = wm * 64 + mi * 16 + (lane >> 2) + h * 8;
                    red[(rloc * 2 + wn) * 2 + 0] = p[mi][h][0];
                    red[(rloc * 2 + wn) * 2 + 1] = p[mi][h][1];
                }
        }
        __syncthreads();
        {
            int row = rowBase + tid;
            if (row < n) {
                float s0 = red[(tid * 2 + 0) * 2 + 0] + red[(tid * 2 + 1) * 2 + 0];
                float s1 = red[(tid * 2 + 0) * 2 + 1] + red[(tid * 2 + 1) * 2 + 1];
                g_Alog[(size_t)row * 2 + 0] = s0 * 0.08838834764831845f;
                g_Alog[(size_t)row * 2 + 1] = s1 * 0.08838834764831845f;
            }
        }
    } else {
#pragma unroll
        for (int mi = 0; mi < 4; mi++)
#pragma unroll
            for (int h = 0; h < 2; h++) {
                int row = rowBase + wm * 64 + mi * 16 + (lane >> 2) + h * 8;
                if (row < n) {
#pragma unroll
                    for (int ni = 0; ni < 8; ni++) {
                        int col = colBase + wn * 64 + ni * 8 + (lane & 3) * 2;
                        float v0 = fmaxf(acc[mi][ni][h * 2 + 0] + __ldg(&bias[col]), 0.f);
                        float v1 = fmaxf(acc[mi][ni][h * 2 + 1] + __ldg(&bias[col + 1]), 0.f);
                        size_t oidx = (size_t)row * DD + col;
                        __nv_bfloat16 h0, l0, h1, l1;
                        split2(v0, h0, l0);
                        split2(v1, h1, l1);
                        *(__nv_bfloat162*)(g_fh + oidx) = __nv_bfloat162(h0, h1);
                        *(__nv_bfloat162*)(g_fl + oidx) = __nv_bfloat162(l0, l1);
                    }
                }
            }
    }
}

// ======================= checkers =======================
__global__ void chk1(const float* __restrict__ feats, const float* __restrict__ W, int n) {
    int s = blockIdx.x * blockDim.x + threadIdx.x;
    int r = (s * 197 + 31) % n;
    int col = (s * 101 + 7) & 511;
    float sc = g_scale[r];
    const float* a = feats + (size_t)r * DD;
    const float* w = W + (size_t)col * DD;
    float acc = 0.f;
    for (int d = 0; d < DD; d++) acc = fmaf(a[d] * sc, w[d], acc);
    float ref = fmaxf(acc, 0.f);
    float got = fget((size_t)r * DD + col);
    if (fabsf(ref - got) > 5e-3f + 1e-3f * fabsf(ref)) g_bad[0] = 1;
}
__global__ void chkQ(const float* __restrict__ Wq, const float* __restrict__ bq, int n) {
    __shared__ float s0[128], s1[128];
    int s = blockIdx.x;
    int j = threadIdx.x;
    int r = (s * 1579 + 131) % n;
    const float* w = Wq + (size_t)j * DD;
    float acc = 0.f;
    for (int d = 0; d < DD; d++) acc = fmaf(fget((size_t)r * DD + d), w[d], acc);
    float q = tanhf(acc + bq[j]);
    s0[j] = q * g_qmax[j];
    s1[j] = q * g_qmax[QD + j];
    __syncthreads();
    for (int st = 64; st; st >>= 1) {
        if (j < st) { s0[j] += s0[j + st]; s1[j] += s1[j + st]; }
        __syncthreads();
    }
    if (j == 0) {
        float r0 = s0[0] * 0.08838834764831845f;
        float r1 = s1[0] * 0.08838834764831845f;
        if (fabsf(r0 - g_Alog[(size_t)r * 2 + 0]) > 5e-3f + 1e-3f * fabsf(r0)) g_bad[2] = 1;
        if (fabsf(r1 - g_Alog[(size_t)r * 2 + 1]) > 5e-3f + 1e-3f * fabsf(r1)) g_bad[2] = 1;
    }
}

// ======================= FFMA fallback GEMMs (proven; gated) =================
__global__ void __launch_bounds__(256) fgemm0(const float* __restrict__ Aext,
                                              const float* __restrict__ W,
                                              const float* __restrict__ bias, int n) {
    if (g_bad[0] == 0) return;
    __shared__ float As[8][128];
    __shared__ float Ws[8][128];
    int tid = threadIdx.x;
    int ty = tid >> 4, tx = tid & 15;
    int rowBase = blockIdx.x * 128;
    int colBase = blockIdx.y * 128;
    float acc[8][8];
#pragma unroll
    for (int i = 0; i < 8; i++)
#pragma unroll
        for (int j = 0; j < 8; j++) acc[i][j] = 0.f;

    int ml = tid >> 1;
    int kq = (tid & 1) * 4;
    int arow = rowBase + ml;
    bool avalid = arow < n;
    float sc = avalid ? g_scale[arow] : 1.f;
    const float* Aptr = Aext + (avalid ? (size_t)arow * DD : 0);
    const float* Wptr = W + (size_t)(colBase + ml) * DD;

    for (int kt = 0; kt < DD; kt += 8) {
        float4 av = make_float4(0.f, 0.f, 0.f, 0.f);
        if (avalid) {
            av = *(const float4*)(Aptr + kt + kq);
            av.x *= sc; av.y *= sc; av.z *= sc; av.w *= sc;
        }
        As[kq + 0][ml] = av.x; As[kq + 1][ml] = av.y;
        As[kq + 2][ml] = av.z; As[kq + 3][ml] = av.w;
        float4 wv = *(const float4*)(Wptr + kt + kq);
        Ws[kq + 0][ml] = wv.x; Ws[kq + 1][ml] = wv.y;
        Ws[kq + 2][ml] = wv.z; Ws[kq + 3][ml] = wv.w;
        __syncthreads();
#pragma unroll
        for (int kk = 0; kk < 8; kk++) {
            float a[8], b[8];
            const float4* Ap = (const float4*)&As[kk][ty * 8];
            const float4* Bp = (const float4*)&Ws[kk][tx * 8];
            float4 a0 = Ap[0], a1 = Ap[1];
            float4 b0 = Bp[0], b1 = Bp[1];
            a[0] = a0.x; a[1] = a0.y; a[2] = a0.z; a[3] = a0.w;
            a[4] = a1.x; a[5] = a1.y; a[6] = a1.z; a[7] = a1.w;
            b[0] = b0.x; b[1] = b0.y; b[2] = b0.z; b[3] = b0.w;
            b[4] = b1.x; b[5] = b1.y; b[6] = b1.z; b[7] = b1.w;
#pragma unroll
            for (int i = 0; i < 8; i++)
#pragma unroll
                for (int j = 0; j < 8; j++) acc[i][j] = fmaf(a[i], b[j], acc[i][j]);
        }
        __syncthreads();
    }
#pragma unroll
    for (int i = 0; i < 8; i++) {
        int r = rowBase + ty * 8 + i;
        if (r >= n) continue;
#pragma unroll
        for (int j = 0; j < 8; j++) {
            int o = colBase + tx * 8 + j;
            float v = fmaxf(acc[i][j] + bias[o], 0.f);
            size_t oidx = (size_t)r * DD + o;
            split2(v, g_fh[oidx], g_fl[oidx]);
        }
    }
}

__global__ void __launch_bounds__(256) fgemmq(const float* __restrict__ Wq,
                                              const float* __restrict__ bq, int n) {
    if (g_bad[2] == 0) return;
    __shared__ float As[8][128];
    __shared__ float Ws[8][128];
    __shared__ float pA[2][16][8][16];
    int tid = threadIdx.x;
    int ty = tid >> 4, tx = tid & 15;
    int rowBase = blockIdx.x * 128;
    float acc[8][8];
#pragma unroll
    for (int i = 0; i < 8; i++)
#pragma unroll
        for (int j = 0; j < 8; j++) acc[i][j] = 0.f;

    int ml = tid >> 1;
    int kq = (tid & 1) * 4;
    int arow = rowBase + ml;
    bool avalid = arow < n;
    const size_t foff = avalid ? (size_t)arow * DD : 0;
    const float* Wptr = Wq + (size_t)ml * DD;

    for (int kt = 0; kt < DD; kt += 8) {
        float4 av = make_float4(0.f, 0.f, 0.f, 0.f);
        if (avalid) {
            size_t o = foff + kt + kq;
            av.x = fget(o); av.y = fget(o + 1); av.z = fget(o + 2); av.w = fget(o + 3);
        }
        As[kq + 0][ml] = av.x; As[kq + 1][ml] = av.y;
        As[kq + 2][ml] = av.z; As[kq + 3][ml] = av.w;
        float4 wv = *(const float4*)(Wptr + kt + kq);
        Ws[kq + 0][ml] = wv.x; Ws[kq + 1][ml] = wv.y;
        Ws[kq + 2][ml] = wv.z; Ws[kq + 3][ml] = wv.w;
        __syncthreads();
#pragma unroll
        for (int kk = 0; kk < 8; kk++) {
            float a[8], b[8];
            const float4* Ap = (const float4*)&As[kk][ty * 8];
            const float4* Bp = (const float4*)&Ws[kk][tx * 8];
            float4 a0 = Ap[0], a1 = Ap[1];
            float4 b0 = Bp[0], b1 = Bp[1];
            a[0] = a0.x; a[1] = a0.y; a[2] = a0.z; a[3] = a0.w;
            a[4] = a1.x; a[5] = a1.y; a[6] = a1.z; a[7] = a1.w;
            b[0] = b0.x; b[1] = b0.y; b[2] = b0.z; b[3] = b0.w;
            b[4] = b1.x; b[5] = b1.y; b[6] = b1.z; b[7] = b1.w;
#pragma unroll
            for (int i = 0; i < 8; i++)
#pragma unroll
                for (int j = 0; j < 8; j++) acc[i][j] = fmaf(a[i], b[j], acc[i][j]);
        }
        __syncthreads();
    }

    float p0[8], p1[8];
#pragma unroll
    for (int i = 0; i < 8; i++) { p0[i] = 0.f; p1[i] = 0.f; }
#pragma unroll
    for (int j = 0; j < 8; j++) {
        int o = tx * 8 + j;
        float qm0 = g_qmax[o];
        float qm1 = g_qmax[QD + o];
        float bqo = bq[o];
#pragma unroll
        for (int i = 0; i < 8; i++) {
            float q = tanhf(acc[i][j] + bqo);
            p0[i] = fmaf(q, qm0, p0[i]);
            p1[i] = fmaf(q, qm1, p1[i]);
        }
    }
#pragma unroll
    for (int i = 0; i < 8; i++) {
        pA[0][ty][i][tx] = p0[i];
        pA[1][ty][i][tx] = p1[i];
    }
    __syncthreads();
    int cc = tid >> 7;
    int rem = tid & 127;
    int tyy = rem >> 3, ii = rem & 7;
    float s = 0.f;
#pragma unroll
    for (int t = 0; t < 16; t++) s += pA[cc][tyy][ii][t];
    int r = rowBase + tyy * 8 + ii;
    if (r < n) g_Alog[(size_t)r * 2 + cc] = s * 0.08838834764831845f;
}

// ======================= argmax over c columns =======================
__global__ void cargpart(const float* __restrict__ c, int n) {
    __shared__ float sv[256][2];
    __shared__ int si[256][2];
    float bv0 = -FLT_MAX, bv1 = -FLT_MAX;
    int bi0 = 0x7fffffff, bi1 = 0x7fffffff;
    for (int i = blockIdx.x * blockDim.x + threadIdx.x; i < n; i += gridDim.x * blockDim.x) {
        float v0 = c[(size_t)i * 2];
        float v1 = c[(size_t)i * 2 + 1];
        if (v0 > bv0 || (v0 == bv0 && i < bi0)) { bv0 = v0; bi0 = i; }
        if (v1 > bv1 || (v1 == bv1 && i < bi1)) { bv1 = v1; bi1 = i; }
    }
    sv[threadIdx.x][0] = bv0; si[threadIdx.x][0] = bi0;
    sv[threadIdx.x][1] = bv1; si[threadIdx.x][1] = bi1;
    __syncthreads();
    for (int st = 128; st; st >>= 1) {
        if (threadIdx.x < st) {
#pragma unroll
            for (int cc = 0; cc < 2; cc++) {
                float v = sv[threadIdx.x + st][cc];
                int ii = si[threadIdx.x + st][cc];
                if (v > sv[threadIdx.x][cc] ||
                    (v == sv[threadIdx.x][cc] && ii < si[threadIdx.x][cc])) {
                    sv[threadIdx.x][cc] = v;
                    si[threadIdx.x][cc] = ii;
                }
            }
        }
        __syncthreads();
    }
    if (threadIdx.x == 0) {
        g_cpv[blockIdx.x * 2 + 0] = sv[0][0]; g_cpi[blockIdx.x * 2 + 0] = si[0][0];
        g_cpv[blockIdx.x * 2 + 1] = sv[0][1]; g_cpi[blockIdx.x * 2 + 1] = si[0][1];
    }
}
__global__ void cargfin() {
    int cc = threadIdx.x;
    if (cc < 2) {
        float bv = -FLT_MAX;
        int bi = 0x7fffffff;
        for (int b = 0; b < 128; b++) {
            float v = g_cpv[b * 2 + cc];
            int ii = g_cpi[b * 2 + cc];
            if (v > bv || (v == bv && ii < bi)) { bv = v; bi = ii; }
        }
        g_midx[cc] = bi;
    }
}

// ======================= q_max rows =======================
__global__ void qmaxk(const float* __restrict__ Wq, const float* __restrict__ bq) {
    int t = threadIdx.x;
    int cls = t >> 7, j = t & 127;
    const size_t r = (size_t)g_midx[cls] * DD;
    const float* wrow = Wq + (size_t)j * DD;
    float s = 0.f;
    for (int d = 0; d < DD; d++) s = fmaf(fget(r + d), wrow[d], s);
    g_qmax[cls * QD + j] = tanhf(s + bq[j]);
}

// ======================= fused A-softmax stats =======================
__global__ void astats(int n) {
    __shared__ float sm0[256], ss0[256], sm1[256], ss1[256];
    float m0 = -FLT_MAX, s0 = 0.f, m1 = -FLT_MAX, s1 = 0.f;
    for (int i = blockIdx.x * blockDim.x + threadIdx.x; i < n; i += gridDim.x * blockDim.x) {
        float v0 = g_Alog[(size_t)i * 2];
        float v1 = g_Alog[(size_t)i * 2 + 1];
        if (v0 > m0) { s0 = s0 * expf(m0 - v0) + 1.f; m0 = v0; } else s0 += expf(v0 - m0);
        if (v1 > m1) { s1 = s1 * expf(m1 - v1) + 1.f; m1 = v1; } else s1 += expf(v1 - m1);
    }
    sm0[threadIdx.x] = m0; ss0[threadIdx.x] = s0;
    sm1[threadIdx.x] = m1; ss1[threadIdx.x] = s1;
    __syncthreads();
    for (int st = 128; st; st >>= 1) {
        if (threadIdx.x < st) {
            float mm = sm0[threadIdx.x], sc = ss0[threadIdx.x];
            msmerge(mm, sc, sm0[threadIdx.x + st], ss0[threadIdx.x + st]);
            sm0[threadIdx.x] = mm; ss0[threadIdx.x] = sc;
            mm = sm1[threadIdx.x]; sc = ss1[threadIdx.x];
            msmerge(mm, sc, sm1[threadIdx.x + st], ss1[threadIdx.x + st]);
            sm1[threadIdx.x] = mm; ss1[threadIdx.x] = sc;
        }
        __syncthreads();
    }
    if (threadIdx.x == 0) {
        g_apm[blockIdx.x * 2 + 0] = sm0[0]; g_aps[blockIdx.x * 2 + 0] = ss0[0];
        g_apm[blockIdx.x * 2 + 1] = sm1[0]; g_aps[blockIdx.x * 2 + 1] = ss1[0];
    }
}
__global__ void astats_fin() {
    if (threadIdx.x < 2) {
        int cc = threadIdx.x;
        float m = -FLT_MAX, s = 0.f;
        for (int b = 0; b < 256; b++) msmerge(m, s, g_apm[b * 2 + cc], g_aps[b * 2 + cc]);
        g_amax[cc] = m;
        g_asum[cc] = s;
    }
}
__global__ void anorm(float* __restrict__ out, int n) {
    float m0 = g_amax[0], m1 = g_amax[1];
    float r0 = 1.0f / g_asum[0], r1 = 1.0f / g_asum[1];
    for (int i = blockIdx.x * blockDim.x + threadIdx.x; i < n; i += gridDim.x * blockDim.x) {
        out[2 + (size_t)i * 2] = expf(g_Alog[(size_t)i * 2] - m0) * r0;
        out[2 + (size_t)i * 2 + 1] = expf(g_Alog[(size_t)i * 2 + 1] - m1) * r1;
    }
}

// ======================= T = A^T @ f ; B = T @ Wv^T + bv =======================
__global__ void bpartF(const float* __restrict__ out, int n) {
    int b = blockIdx.x;
    int col = threadIdx.x; // 512
    int chunk = (n + gridDim.x - 1) / gridDim.x;
    int r0 = b * chunk;
    int r1 = min(n, r0 + chunk);
    float a0 = 0.f, a1 = 0.f;
    const float* Aout = out + 2;
    for (int r = r0; r < r1; r++) {
        float A0 = Aout[(size_t)r * 2];
        float A1 = Aout[(size_t)r * 2 + 1];
        float v = fget((size_t)r * DD + col);
        a0 = fmaf(A0, v, a0);
        a1 = fmaf(A1, v, a1);
    }
    g_Bpart[(b * 2 + 0) * DD + col] = a0;
    g_Bpart[(b * 2 + 1) * DD + col] = a1;
}
__global__ void tfin() {
    int col = threadIdx.x; // 512
    float a0 = 0.f, a1 = 0.f;
    for (int b = 0; b < BBLK; b++) {
        a0 += g_Bpart[(b * 2 + 0) * DD + col];
        a1 += g_Bpart[(b * 2 + 1) * DD + col];
    }
    g_T[col] = a0;
    g_T[DD + col] = a1;
}
__global__ void bmm(const float* __restrict__ Wv, const float* __restrict__ bv,
                    float* __restrict__ out, int n) {
    int j = blockIdx.x * blockDim.x + threadIdx.x;  // <<<2,256>>>
    if (j >= DD) return;
    const float* w = Wv + (size_t)j * DD;
    float a0 = 0.f, a1 = 0.f;
    for (int d = 0; d < DD; d++) {
        float wv = w[d];
        a0 = fmaf(g_T[d], wv, a0);
        a1 = fmaf(g_T[DD + d], wv, a1);
    }
    a0 += bv[j];
    a1 += bv[j];
    g_B[j] = a0;
    g_B[DD + j] = a1;
    size_t off = 2 + (size_t)2 * n;
    out[off + j] = a0;
    out[off + DD + j] = a1;
}

// ======================= Cout =======================
__global__ void coutk(const float* __restrict__ Wf, const float* __restrict__ bf,
                      float* __restrict__ out) {
    __shared__ float s0[256], s1[256];
    int t = threadIdx.x;
    float a0 = 0.f, a1 = 0.f;
    for (int idx = t; idx < 1024; idx += 256) {
        float b = g_B[idx];
        a0 = fmaf(b, Wf[idx], a0);
        a1 = fmaf(b, Wf[1024 + idx], a1);
    }
    s0[t] = a0; s1[t] = a1;
    __syncthreads();
    for (int st = 128; st; st >>= 1) {
        if (t < st) { s0[t] += s0[t + st]; s1[t] += s1[t + st]; }
        __syncthreads();
    }
    if (t == 0) {
        out[0] = s0[0] + bf[0];
        out[1] = s1[0] + bf[1];
    }
}

// ======================= launch =======================
extern "C" void kernel_launch(void* const* d_in, const int* in_sizes, int n_in,
                              void* d_out, int out_size) {
    const float* feats = (const float*)d_in[0];
    const float* c     = (const float*)d_in[1];
    const float* sp    = (const float*)d_in[2];
    const float* Wlin  = (const float*)d_in[3];
    const float* blin  = (const float*)d_in[4];
    const float* Wq    = (const float*)d_in[5];
    const float* bq    = (const float*)d_in[6];
    const float* Wv    = (const float*)d_in[7];
    const float* bv    = (const float*)d_in[8];
    const float* Wf    = (const float*)d_in[9];
    const float* bf    = (const float*)d_in[10];
    float* out = (float*)d_out;

    int n = in_sizes[2];
    int k = (int)(0.2 * (double)n);
    int rowTiles = (n + 127) / 128;

    // 1) bottom-k select (resets g_bad)
    init_sel<<<1, 256>>>(k);
    for (int p = 0; p < 4; p++) {
        hist_kernel<<<256, 256>>>(sp, n, p);
        scan_kernel<<<1, 256>>>(p);
    }

    // 2) fused zero + instance-softmax stats -> scale
    pstats<<<256, 256>>>(sp, n);
    pstats_fin<<<1, 256>>>();
    scalek<<<256, 256>>>(n);

    // 3) conversions (device-symbol writes only)
    convWlin<<<256, 256>>>(Wlin);
    convWq<<<64, 256>>>(Wq);
    convA<<<2048, 256>>>(feats, n);

    // 4) f GEMM: split-bf16 MMA (128-thread, 64x64 warp tiles, cp.async)
    mma_gemm<0><<<dim3(4, rowTiles), 128>>>(blin, n);
    chk1<<<4, 128>>>(feats, Wlin, n);
    fgemm0<<<dim3(rowTiles, 4), 256>>>(feats, Wlin, blin, n);

    // 5) critical instances and q_max
    cargpart<<<128, 256>>>(c, n);
    cargfin<<<1, 32>>>();
    qmaxk<<<1, 256>>>(Wq, bq);

    // 6) Q GEMM + A logits
    mma_gemm<2><<<dim3(1, rowTiles), 128>>>(bq, n);
    chkQ<<<64, 128>>>(Wq, bq, n);
    fgemmq<<<rowTiles, 256>>>(Wq, bq, n);

    // 7) fused column-softmax stats + normalize -> out[2 : 2+2n]
    astats<<<256, 256>>>(n);
    astats_fin<<<1, 32>>>();
    anorm<<<256, 256>>>(out, n);

    // 8) B = (A^T @ f) @ Wv^T + bv   (V GEMM eliminated)
    bpartF<<<BBLK, 512>>>(out, n);
    tfin<<<1, 512>>>();
    bmm<<<2, 256>>>(Wv, bv, out, n);

    // 9) Cout
    coutk<<<1, 256>>>(Wf, bf, out);
}